// round 10
// baseline (speedup 1.0000x reference)
#include <cuda_runtime.h>
#include <math_constants.h>
#include <stdint.h>

// Problem constants
#define CB   16
#define CL   512
#define CDM  768
#define CS   2048
#define CDL  4096
#define CH   8
#define CE   96
#define CHE  768   // H*E

// Scratch (allocation-free: device globals)
__device__ float g_Q[(size_t)CB * CL * CHE];   // 8192 x 768 (tf32-rounded)
__device__ float g_K[(size_t)CS * CHE];        // 2048 x 768 (tf32-rounded)
__device__ float g_V[(size_t)CS * CHE];        // 2048 x 768 (tf32-rounded)
__device__ float g_rep[(size_t)CB * CL * CHE]; // 8192 x 768 (tf32-rounded)
// Split-K partials for K/V projections: z in [0,4): (split = z>>1, K/V = z&1)
__device__ float g_kvpart[(size_t)4 * CS * CHE];   // 24 MB

__device__ __forceinline__ float rna_tf32(float x) {
    uint32_t r;
    asm("cvt.rna.tf32.f32 %0, %1;" : "=r"(r) : "f"(x));
    return __uint_as_float(r);
}

__device__ __forceinline__ uint32_t rna_tf32_u(float x) {
    uint32_t r;
    asm("cvt.rna.tf32.f32 %0, %1;" : "=r"(r) : "f"(x));
    return r;
}

__device__ __forceinline__ float ex2(float x) {
    float y;
    asm("ex2.approx.f32 %0, %1;" : "=f"(y) : "f"(x));
    return y;
}

__device__ __forceinline__ void mma_tf32(float* d, const uint32_t* a, const uint32_t* b) {
    asm volatile(
        "mma.sync.aligned.m16n8k8.row.col.f32.tf32.tf32.f32 "
        "{%0,%1,%2,%3}, {%4,%5,%6,%7}, {%8,%9}, {%0,%1,%2,%3};"
        : "+f"(d[0]), "+f"(d[1]), "+f"(d[2]), "+f"(d[3])
        : "r"(a[0]), "r"(a[1]), "r"(a[2]), "r"(a[3]), "r"(b[0]), "r"(b[1]));
}

__device__ __forceinline__ void cp_async16(uint32_t dst, const void* src) {
    asm volatile("cp.async.cg.shared.global [%0], [%1], 16;\n" :: "r"(dst), "l"(src));
}

// ============================================================================
// TF32 mma.sync GEMM core, 64x64 warp tiles; rna conversion at fragment load
// (identical numerics to pre-rounded inputs; cvt hides under tensor floor).
// 128x128x32 block tile, 128 threads = 4 warps (2Mx2N), 3-stage cp.async.
// ============================================================================
#define GBM 128
#define GBN 128
#define GBK 32
#define AS_STRIDE 36
#define BS_STRIDE 136
#define AS_ELEMS (GBM * AS_STRIDE)
#define BS_ELEMS (GBK * BS_STRIDE)
#define GEMM_SMEM (3 * (AS_ELEMS + BS_ELEMS) * 4)

struct GemmCtx { int tid, rb, nb, g, c; };

__device__ __forceinline__ void gemm_ctx_init(GemmCtx& x) {
    const int tid = threadIdx.x;
    const int wid = tid >> 5;
    const int lane = tid & 31;
    x.tid = tid;
    x.rb = (wid & 1) * 64;
    x.nb = (wid >> 1) * 64;
    x.g = lane >> 2;
    x.c = lane & 3;
}

// acc[4][8][4]: mt over 4 m16 tiles, nt over 8 n8 tiles
__device__ __forceinline__ void gemm_core(
    const float* __restrict__ A, const float* __restrict__ Bg,
    int bm, int bn, int N, int K, int k_begin, int k_len,
    float* As, float* Bs, float acc[4][8][4], const GemmCtx& x)
{
    const uint32_t sAs = (uint32_t)__cvta_generic_to_shared(As);
    const uint32_t sBs = (uint32_t)__cvta_generic_to_shared(Bs);
    const int tid = x.tid;

    auto load_tiles = [&](int stg, int kk) {
        const uint32_t a_base = sAs + stg * (AS_ELEMS * 4);
        const uint32_t b_base = sBs + stg * (BS_ELEMS * 4);
#pragma unroll
        for (int j = 0; j < 8; ++j) {
            const int idx = tid + j * 128;          // 0..1023
            const int rA = idx >> 3;                // 0..127
            const int cA = (idx & 7) << 2;          // 0..28
            cp_async16(a_base + (rA * AS_STRIDE + cA) * 4,
                       A + (size_t)(bm + rA) * K + kk + cA);
            const int rB = idx >> 5;                // 0..31
            const int cB = (idx & 31) << 2;         // 0..124
            cp_async16(b_base + (rB * BS_STRIDE + cB) * 4,
                       Bg + (size_t)(kk + rB) * N + bn + cB);
        }
        asm volatile("cp.async.commit_group;\n" ::);
    };

    const int NC = k_len / GBK;
    load_tiles(0, k_begin);
    load_tiles(1, k_begin + GBK);

    for (int i = 0; i < NC; ++i) {
        if (i + 1 < NC) asm volatile("cp.async.wait_group 1;\n" ::);
        else            asm volatile("cp.async.wait_group 0;\n" ::);
        __syncthreads();
        if (i + 2 < NC)
            load_tiles((i + 2) % 3, k_begin + (i + 2) * GBK);

        const float* Ab = As + (i % 3) * AS_ELEMS;
        const float* Bb = Bs + (i % 3) * BS_ELEMS;

#pragma unroll
        for (int ks = 0; ks < 4; ++ks) {
            const int k0 = ks * 8;
            uint32_t af[4][4], bf[8][2];
#pragma unroll
            for (int mt = 0; mt < 4; ++mt) {
                const float* p0 = Ab + (x.rb + mt * 16 + x.g) * AS_STRIDE + k0 + x.c;
                const float* p1 = p0 + 8 * AS_STRIDE;
                af[mt][0] = rna_tf32_u(p0[0]);
                af[mt][1] = rna_tf32_u(p1[0]);
                af[mt][2] = rna_tf32_u(p0[4]);
                af[mt][3] = rna_tf32_u(p1[4]);
            }
#pragma unroll
            for (int nt = 0; nt < 8; ++nt) {
                const float* p = Bb + (k0 + x.c) * BS_STRIDE + x.nb + nt * 8 + x.g;
                bf[nt][0] = rna_tf32_u(p[0]);
                bf[nt][1] = rna_tf32_u(p[4 * BS_STRIDE]);
            }
#pragma unroll
            for (int mt = 0; mt < 4; ++mt)
#pragma unroll
                for (int nt = 0; nt < 8; ++nt)
                    mma_tf32(acc[mt][nt], af[mt], bf[nt]);
        }
    }
}

__device__ __forceinline__ void gemm_zero(float acc[4][8][4]) {
#pragma unroll
    for (int mt = 0; mt < 4; ++mt)
#pragma unroll
        for (int nt = 0; nt < 8; ++nt)
#pragma unroll
            for (int r = 0; r < 4; ++r) acc[mt][nt][r] = 0.0f;
}

// Generic GEMM with bias (+optional rna round) epilogue.
__global__ __launch_bounds__(128, 2)
void gemm_tf32(const float* __restrict__ A, const float* __restrict__ Bg,
               const float* __restrict__ bias, float* __restrict__ C,
               int M, int N, int K, int round_out)
{
    extern __shared__ float smem[];
    GemmCtx x; gemm_ctx_init(x);
    const int bm = blockIdx.y * GBM;
    const int bn = blockIdx.x * GBN;

    float acc[4][8][4];
    gemm_zero(acc);
    gemm_core(A, Bg, bm, bn, N, K, 0, K, smem, smem + 3 * AS_ELEMS, acc, x);

#pragma unroll
    for (int mt = 0; mt < 4; ++mt) {
        const int row0 = bm + x.rb + mt * 16 + x.g;
#pragma unroll
        for (int nt = 0; nt < 8; ++nt) {
            const int col = bn + x.nb + nt * 8 + 2 * x.c;
            const float2 bv = *(const float2*)&bias[col];
            float2 o0 = { acc[mt][nt][0] + bv.x, acc[mt][nt][1] + bv.y };
            float2 o1 = { acc[mt][nt][2] + bv.x, acc[mt][nt][3] + bv.y };
            if (round_out) {
                o0.x = rna_tf32(o0.x); o0.y = rna_tf32(o0.y);
                o1.x = rna_tf32(o1.x); o1.y = rna_tf32(o1.y);
            }
            *(float2*)&C[(size_t)row0 * N + col] = o0;
            *(float2*)&C[(size_t)(row0 + 8) * N + col] = o1;
        }
    }
}

// Fused projection kernel, 1-D grid of 768 CTAs:
//  cta <  384: KV split-K partial (z=cta/96: split=z>>1, V=z&1, K half = 2048)
//  cta >= 384: Q projection (K=768), bias + rna epilogue
__global__ __launch_bounds__(128, 2)
void proj_fused(const float* __restrict__ Tgt, const float* __restrict__ Src,
                const float* __restrict__ Wq, const float* __restrict__ bq,
                float* __restrict__ Qout,
                const float* __restrict__ Wk, const float* __restrict__ Wv,
                float* __restrict__ Part)
{
    extern __shared__ float smem[];
    GemmCtx x; gemm_ctx_init(x);
    const int cta = blockIdx.x;

    float acc[4][8][4];
    gemm_zero(acc);

    if (cta < 384) {
        const int z = cta / 96;                 // 0..3
        const int rem = cta % 96;
        const int bm = (rem / 6) * GBM;
        const int bn = (rem % 6) * GBN;
        const float* Bg = (z & 1) ? Wv : Wk;
        float* C = Part + (size_t)z * CS * CHE;

        gemm_core(Src, Bg, bm, bn, CHE, CDL, (z >> 1) * (CDL / 2), CDL / 2,
                  smem, smem + 3 * AS_ELEMS, acc, x);

#pragma unroll
        for (int mt = 0; mt < 4; ++mt) {
            const int row0 = bm + x.rb + mt * 16 + x.g;
#pragma unroll
            for (int nt = 0; nt < 8; ++nt) {
                const int col = bn + x.nb + nt * 8 + 2 * x.c;
                *(float2*)&C[(size_t)row0 * CHE + col] =
                    make_float2(acc[mt][nt][0], acc[mt][nt][1]);
                *(float2*)&C[(size_t)(row0 + 8) * CHE + col] =
                    make_float2(acc[mt][nt][2], acc[mt][nt][3]);
            }
        }
    } else {
        const int idx = cta - 384;
        const int bm = (idx / 6) * GBM;
        const int bn = (idx % 6) * GBN;

        gemm_core(Tgt, Wq, bm, bn, CHE, CDM, 0, CDM,
                  smem, smem + 3 * AS_ELEMS, acc, x);

#pragma unroll
        for (int mt = 0; mt < 4; ++mt) {
            const int row0 = bm + x.rb + mt * 16 + x.g;
#pragma unroll
            for (int nt = 0; nt < 8; ++nt) {
                const int col = bn + x.nb + nt * 8 + 2 * x.c;
                const float2 bv = *(const float2*)&bq[col];
                float2 o0 = { rna_tf32(acc[mt][nt][0] + bv.x),
                              rna_tf32(acc[mt][nt][1] + bv.y) };
                float2 o1 = { rna_tf32(acc[mt][nt][2] + bv.x),
                              rna_tf32(acc[mt][nt][3] + bv.y) };
                *(float2*)&Qout[(size_t)row0 * CHE + col] = o0;
                *(float2*)&Qout[(size_t)(row0 + 8) * CHE + col] = o1;
            }
        }
    }
}

// Reduce the 2 split-K partials for K and V, add bias, rna-round.
__global__ void reduce_kv(const float* __restrict__ part,
                          const float* __restrict__ bk, const float* __restrict__ bv,
                          float* __restrict__ Kout, float* __restrict__ Vout)
{
    const int i4 = blockIdx.x * blockDim.x + threadIdx.x;
    const int n4 = CS * CHE / 4;
    if (i4 >= n4) return;
    const size_t MN = (size_t)CS * CHE;
    const size_t off = (size_t)i4 * 4;
    const int col = (int)(off % CHE);

    float4 sk = make_float4(0.f, 0.f, 0.f, 0.f);
    float4 sv = make_float4(0.f, 0.f, 0.f, 0.f);
#pragma unroll
    for (int s = 0; s < 2; ++s) {
        float4 pk = *(const float4*)&part[(size_t)(2 * s) * MN + off];
        float4 pv = *(const float4*)&part[(size_t)(2 * s + 1) * MN + off];
        sk.x += pk.x; sk.y += pk.y; sk.z += pk.z; sk.w += pk.w;
        sv.x += pv.x; sv.y += pv.y; sv.z += pv.z; sv.w += pv.w;
    }
    float4 bkv = *(const float4*)&bk[col];
    float4 bvv = *(const float4*)&bv[col];
    float4 ok = { rna_tf32(sk.x + bkv.x), rna_tf32(sk.y + bkv.y),
                  rna_tf32(sk.z + bkv.z), rna_tf32(sk.w + bkv.w) };
    float4 ov = { rna_tf32(sv.x + bvv.x), rna_tf32(sv.y + bvv.y),
                  rna_tf32(sv.z + bvv.z), rna_tf32(sv.w + bvv.w) };
    *(float4*)&Kout[off] = ok;
    *(float4*)&Vout[off] = ov;
}

// ============================================================================
// Tensor-core flash attention (unchanged from R4/R8/R9).
// ============================================================================
#define SQ  128
#define SC  64
#define QST 100
#define KST 100
#define VST 104
#define PST 68

#define ATTN_SMEM ((SQ * QST + 2 * SC * KST + 2 * SC * VST + SQ * PST) * 4)

__global__ __launch_bounds__(256, 1)
void attn_tc()
{
    extern __shared__ float sm[];
    float* Qs = sm;
    float* Ks = Qs + SQ * QST;
    float* Vs = Ks + 2 * SC * KST;
    float* Ps = Vs + 2 * SC * VST;

    const int tid  = threadIdx.x;
    const int w    = tid >> 5;
    const int lane = tid & 31;
    const int g = lane >> 2;
    const int c = lane & 3;
    const int bh = blockIdx.y;
    const int b = bh >> 3;
    const int h = bh & 7;
    const int q0 = blockIdx.x * SQ;
    const int r0 = w * 16 + g;

    const float qs = 0.1020620726159658f * 1.4426950408889634f;

    for (int i = tid; i < SQ * (CE / 4); i += 256) {
        const int r = i / (CE / 4);
        const int c4 = (i % (CE / 4)) * 4;
        float4 v = *(const float4*)&g_Q[((size_t)(b * CL + q0 + r)) * CHE + h * CE + c4];
        Qs[r * QST + c4 + 0] = rna_tf32(v.x * qs);
        Qs[r * QST + c4 + 1] = rna_tf32(v.y * qs);
        Qs[r * QST + c4 + 2] = rna_tf32(v.z * qs);
        Qs[r * QST + c4 + 3] = rna_tf32(v.w * qs);
    }
    __syncthreads();

    uint32_t qf[12][4];
#pragma unroll
    for (int ks = 0; ks < 12; ++ks) {
        const float* p = Qs + r0 * QST + ks * 8 + c;
        qf[ks][0] = __float_as_uint(p[0]);
        qf[ks][1] = __float_as_uint(p[8 * QST]);
        qf[ks][2] = __float_as_uint(p[4]);
        qf[ks][3] = __float_as_uint(p[8 * QST + 4]);
    }

    float oacc[12][4];
#pragma unroll
    for (int nt = 0; nt < 12; ++nt)
#pragma unroll
        for (int r = 0; r < 4; ++r) oacc[nt][r] = 0.0f;
    float m0 = -1e30f, m1 = -1e30f, l0 = 0.0f, l1 = 0.0f;

    const uint32_t sKs = (uint32_t)__cvta_generic_to_shared(Ks);
    const uint32_t sVs = (uint32_t)__cvta_generic_to_shared(Vs);

    auto load_kv = [&](int bufi, int s0) {
#pragma unroll
        for (int j = 0; j < 6; ++j) {
            const int idx = tid + j * 256;
            const int r = idx / (CE / 4);
            const int c4 = (idx % (CE / 4)) * 4;
            const size_t off = ((size_t)(s0 + r)) * CHE + h * CE + c4;
            cp_async16(sKs + (bufi * SC * KST + r * KST + c4) * 4, &g_K[off]);
            cp_async16(sVs + (bufi * SC * VST + r * VST + c4) * 4, &g_V[off]);
        }
        asm volatile("cp.async.commit_group;\n" ::);
    };

    load_kv(0, 0);
    int buf = 0;

    for (int it = 0; it < CS / SC; ++it) {
        if (it + 1 < CS / SC) {
            load_kv(buf ^ 1, (it + 1) * SC);
            asm volatile("cp.async.wait_group 1;\n" ::);
        } else {
            asm volatile("cp.async.wait_group 0;\n" ::);
        }
        __syncthreads();

        const float* Kb = Ks + buf * SC * KST;
        const float* Vb = Vs + buf * SC * VST;

        float sacc[8][4];
#pragma unroll
        for (int nt = 0; nt < 8; ++nt)
#pragma unroll
            for (int r = 0; r < 4; ++r) sacc[nt][r] = 0.0f;

#pragma unroll
        for (int ks = 0; ks < 12; ++ks) {
            uint32_t kf[8][2];
#pragma unroll
            for (int nt = 0; nt < 8; ++nt) {
                const float* p = Kb + (nt * 8 + g) * KST + ks * 8 + c;
                kf[nt][0] = __float_as_uint(p[0]);
                kf[nt][1] = __float_as_uint(p[4]);
            }
#pragma unroll
            for (int nt = 0; nt < 8; ++nt)
                mma_tf32(sacc[nt], qf[ks], kf[nt]);
        }

        float cm0 = -1e30f, cm1 = -1e30f;
#pragma unroll
        for (int nt = 0; nt < 8; ++nt) {
            cm0 = fmaxf(cm0, fmaxf(sacc[nt][0], sacc[nt][1]));
            cm1 = fmaxf(cm1, fmaxf(sacc[nt][2], sacc[nt][3]));
        }
        cm0 = fmaxf(cm0, __shfl_xor_sync(0xffffffffu, cm0, 1));
        cm0 = fmaxf(cm0, __shfl_xor_sync(0xffffffffu, cm0, 2));
        cm1 = fmaxf(cm1, __shfl_xor_sync(0xffffffffu, cm1, 1));
        cm1 = fmaxf(cm1, __shfl_xor_sync(0xffffffffu, cm1, 2));

        const float nm0 = fmaxf(m0, cm0);
        const float nm1 = fmaxf(m1, cm1);
        const float sc0 = ex2(m0 - nm0);
        const float sc1 = ex2(m1 - nm1);
        m0 = nm0; m1 = nm1;

        float rs0 = 0.0f, rs1 = 0.0f;
#pragma unroll
        for (int nt = 0; nt < 8; ++nt) {
            const float p00 = ex2(sacc[nt][0] - m0);
            const float p01 = ex2(sacc[nt][1] - m0);
            const float p10 = ex2(sacc[nt][2] - m1);
            const float p11 = ex2(sacc[nt][3] - m1);
            rs0 += p00 + p01;
            rs1 += p10 + p11;
            float* pr0 = Ps + r0 * PST + nt * 8 + 2 * c;
            pr0[0] = rna_tf32(p00);
            pr0[1] = rna_tf32(p01);
            float* pr1 = Ps + (r0 + 8) * PST + nt * 8 + 2 * c;
            pr1[0] = rna_tf32(p10);
            pr1[1] = rna_tf32(p11);
        }
        rs0 += __shfl_xor_sync(0xffffffffu, rs0, 1);
        rs0 += __shfl_xor_sync(0xffffffffu, rs0, 2);
        rs1 += __shfl_xor_sync(0xffffffffu, rs1, 1);
        rs1 += __shfl_xor_sync(0xffffffffu, rs1, 2);
        l0 = l0 * sc0 + rs0;
        l1 = l1 * sc1 + rs1;

#pragma unroll
        for (int nt = 0; nt < 12; ++nt) {
            oacc[nt][0] *= sc0; oacc[nt][1] *= sc0;
            oacc[nt][2] *= sc1; oacc[nt][3] *= sc1;
        }
        __syncwarp();

#pragma unroll
        for (int ks = 0; ks < 8; ++ks) {
            uint32_t pf[4];
            const float* pp = Ps + r0 * PST + ks * 8 + c;
            pf[0] = __float_as_uint(pp[0]);
            pf[1] = __float_as_uint(pp[8 * PST]);
            pf[2] = __float_as_uint(pp[4]);
            pf[3] = __float_as_uint(pp[8 * PST + 4]);
#pragma unroll
            for (int nt = 0; nt < 12; ++nt) {
                const float* vp = Vb + (ks * 8 + c) * VST + nt * 8 + g;
                uint32_t vf[2];
                vf[0] = __float_as_uint(vp[0]);
                vf[1] = __float_as_uint(vp[4 * VST]);
                mma_tf32(oacc[nt], pf, vf);
            }
        }
        __syncthreads();
        buf ^= 1;
    }

    const float inv0 = 1.0f / l0;
    const float inv1 = 1.0f / l1;
    const size_t row0 = ((size_t)(b * CL + q0 + r0)) * CHE + h * CE;
    const size_t row1 = ((size_t)(b * CL + q0 + r0 + 8)) * CHE + h * CE;
#pragma unroll
    for (int nt = 0; nt < 12; ++nt) {
        const int col = nt * 8 + 2 * c;
        float2 o0 = { rna_tf32(oacc[nt][0] * inv0), rna_tf32(oacc[nt][1] * inv0) };
        float2 o1 = { rna_tf32(oacc[nt][2] * inv1), rna_tf32(oacc[nt][3] * inv1) };
        *(float2*)&g_rep[row0 + col] = o0;
        *(float2*)&g_rep[row1 + col] = o1;
    }
}

// ============================================================================
// Launch
// ============================================================================
extern "C" void kernel_launch(void* const* d_in, const int* in_sizes, int n_in,
                              void* d_out, int out_size)
{
    const float* target = (const float*)d_in[0];
    const float* source = (const float*)d_in[1];
    const float* Wq = (const float*)d_in[2];
    const float* bq = (const float*)d_in[3];
    const float* Wk = (const float*)d_in[4];
    const float* bk = (const float*)d_in[5];
    const float* Wv = (const float*)d_in[6];
    const float* bv = (const float*)d_in[7];
    const float* Wo = (const float*)d_in[8];
    const float* bo = (const float*)d_in[9];
    float* out = (float*)d_out;

    float *Qp, *Kp, *Vp, *Rp, *Pp;
    cudaGetSymbolAddress((void**)&Qp, g_Q);
    cudaGetSymbolAddress((void**)&Kp, g_K);
    cudaGetSymbolAddress((void**)&Vp, g_V);
    cudaGetSymbolAddress((void**)&Rp, g_rep);
    cudaGetSymbolAddress((void**)&Pp, g_kvpart);

    cudaFuncSetAttribute(gemm_tf32, cudaFuncAttributeMaxDynamicSharedMemorySize,
                         GEMM_SMEM);
    cudaFuncSetAttribute(proj_fused, cudaFuncAttributeMaxDynamicSharedMemorySize,
                         GEMM_SMEM);
    cudaFuncSetAttribute(attn_tc, cudaFuncAttributeMaxDynamicSharedMemorySize,
                         ATTN_SMEM);

    // Fused Q projection + K/V split-K(x2) partials (768 CTAs, 128 threads)
    proj_fused<<<768, 128, GEMM_SMEM>>>(target, source, Wq, bq, Qp, Wk, Wv, Pp);

    // Reduce K/V partials (+bias, rna)
    {
        const int n4 = CS * CHE / 4;
        reduce_kv<<<(n4 + 255) / 256, 256>>>(Pp, bk, bv, Kp, Vp);
    }

    // Attention -> rep (tensor-core, rounded epilogue)
    attn_tc<<<dim3(CL / SQ, CB * CH), dim3(256), ATTN_SMEM>>>();

    // out = rep @ Wo + bo   (8192 x 4096, K=768), full fp32 epilogue
    gemm_tf32<<<dim3(CDL / GBN, (CB * CL) / GBM), 128, GEMM_SMEM>>>(
        Rp, Wo, bo, out, CB * CL, CDL, CHE, 0);
}

// round 11
// speedup vs baseline: 1.3258x; 1.3258x over previous
#include <cuda_runtime.h>
#include <cuda_fp16.h>
#include <stdint.h>

// Problem constants
#define CB   16
#define CL   512
#define CDM  768
#define CS   2048
#define CDL  4096
#define CH   8
#define CE   96
#define CHE  768   // H*E

// Scratch (allocation-free: device globals)
__device__ float  g_Q[(size_t)CB * CL * CHE];   // fp32, tf32-rounded (attn input)
__device__ float  g_K[(size_t)CS * CHE];
__device__ float  g_V[(size_t)CS * CHE];
__device__ __half g_repH[(size_t)CB * CL * CHE]; // attn output, fp16 (out-proj A)
// fp16 staged GEMM operands (A matrices [M][K], weights transposed [N][K])
__device__ __half g_tgtH[(size_t)CB * CL * CDM];
__device__ __half g_srcH[(size_t)CS * CDL];
__device__ __half g_wqT[(size_t)CHE * CDM];     // [768][768]
__device__ __half g_wkT[(size_t)CHE * CDL];     // [768][4096]
__device__ __half g_wvT[(size_t)CHE * CDL];     // [768][4096]
__device__ __half g_woT[(size_t)CDL * CHE];     // [4096][768]
// Split-K partials for K/V projections: z in [0,4): (split = z>>1, K/V = z&1)
__device__ float g_kvpart[(size_t)4 * CS * CHE];   // 24 MB

__device__ __forceinline__ float rna_tf32(float x) {
    uint32_t r;
    asm("cvt.rna.tf32.f32 %0, %1;" : "=r"(r) : "f"(x));
    return __uint_as_float(r);
}

__device__ __forceinline__ float ex2(float x) {
    float y;
    asm("ex2.approx.f32 %0, %1;" : "=f"(y) : "f"(x));
    return y;
}

__device__ __forceinline__ void mma_tf32(float* d, const uint32_t* a, const uint32_t* b) {
    asm volatile(
        "mma.sync.aligned.m16n8k8.row.col.f32.tf32.tf32.f32 "
        "{%0,%1,%2,%3}, {%4,%5,%6,%7}, {%8,%9}, {%0,%1,%2,%3};"
        : "+f"(d[0]), "+f"(d[1]), "+f"(d[2]), "+f"(d[3])
        : "r"(a[0]), "r"(a[1]), "r"(a[2]), "r"(a[3]), "r"(b[0]), "r"(b[1]));
}

__device__ __forceinline__ void mma_f16(float* d, const uint32_t* a, const uint32_t* b) {
    asm volatile(
        "mma.sync.aligned.m16n8k16.row.col.f32.f16.f16.f32 "
        "{%0,%1,%2,%3}, {%4,%5,%6,%7}, {%8,%9}, {%0,%1,%2,%3};"
        : "+f"(d[0]), "+f"(d[1]), "+f"(d[2]), "+f"(d[3])
        : "r"(a[0]), "r"(a[1]), "r"(a[2]), "r"(a[3]), "r"(b[0]), "r"(b[1]));
}

__device__ __forceinline__ void cp_async16(uint32_t dst, const void* src) {
    asm volatile("cp.async.cg.shared.global [%0], [%1], 16;\n" :: "r"(dst), "l"(src));
}

// ============================================================================
// Pre-passes: fp32 -> fp16 copy, and fp32 [K][N] -> fp16 [N][K] transpose
// ============================================================================
__global__ void cvt16(const float4* __restrict__ src, __half2* __restrict__ dst,
                      int n4)
{
    int i = blockIdx.x * blockDim.x + threadIdx.x;
    if (i < n4) {
        float4 v = src[i];
        dst[2 * i + 0] = __floats2half2_rn(v.x, v.y);
        dst[2 * i + 1] = __floats2half2_rn(v.z, v.w);
    }
}

__global__ void transpose_h(const float* __restrict__ in, __half* __restrict__ out,
                            int K, int N)
{
    __shared__ float t[32][33];
    const int n0 = blockIdx.x * 32;
    const int k0 = blockIdx.y * 32;
    const int xx = threadIdx.x;
    const int yy = threadIdx.y;
#pragma unroll
    for (int dy = 0; dy < 32; dy += 8)
        t[yy + dy][xx] = in[(size_t)(k0 + yy + dy) * N + n0 + xx];
    __syncthreads();
#pragma unroll
    for (int dy = 0; dy < 32; dy += 8)
        out[(size_t)(n0 + yy + dy) * K + k0 + xx] = __float2half_rn(t[xx][yy + dy]);
}

// ============================================================================
// FP16 mma.sync GEMM core (m16n8k16). 128x128x32 block, 4 warps (2Mx2N),
// 64x64 warp tiles, 3-stage cp.async. A [M][K] fp16, Bt [N][K] fp16 (both
// K-contiguous); tiles [128 rows][40 halves] (stride 40 -> conflict-free).
// ============================================================================
#define HBK 32
#define HST 40                       // halves per tile row
#define HTILE_HALVES (128 * HST)     // 5120
#define HTILE_BYTES  (HTILE_HALVES * 2)
#define GEMM_SMEM_H  (3 * 2 * HTILE_BYTES)   // 61440 B

struct GemmCtx { int tid, rb, nb, g, c; };

__device__ __forceinline__ void gemm_ctx_init(GemmCtx& x) {
    const int tid = threadIdx.x;
    const int wid = tid >> 5;
    const int lane = tid & 31;
    x.tid = tid;
    x.rb = (wid & 1) * 64;
    x.nb = (wid >> 1) * 64;
    x.g = lane >> 2;
    x.c = lane & 3;
}

__device__ __forceinline__ void gemm_zero(float acc[4][8][4]) {
#pragma unroll
    for (int mt = 0; mt < 4; ++mt)
#pragma unroll
        for (int nt = 0; nt < 8; ++nt)
#pragma unroll
            for (int r = 0; r < 4; ++r) acc[mt][nt][r] = 0.0f;
}

__device__ __forceinline__ void gemm_core_h(
    const __half* __restrict__ A, const __half* __restrict__ Bt,
    int bm, int bn, int K, int k_begin, int k_len,
    __half* As, __half* Bs, float acc[4][8][4], const GemmCtx& x)
{
    const uint32_t sA = (uint32_t)__cvta_generic_to_shared(As);
    const uint32_t sB = (uint32_t)__cvta_generic_to_shared(Bs);
    const int tid = x.tid;

    auto load_tiles = [&](int stg, int kk) {
        const uint32_t ab = sA + stg * HTILE_BYTES;
        const uint32_t bb = sB + stg * HTILE_BYTES;
#pragma unroll
        for (int j = 0; j < 4; ++j) {
            const int idx = tid + j * 128;   // 0..511
            const int r = idx >> 2;          // 0..127
            const int q = (idx & 3) << 3;    // half offset: 0,8,16,24
            cp_async16(ab + (r * HST + q) * 2, A + (size_t)(bm + r) * K + kk + q);
            cp_async16(bb + (r * HST + q) * 2, Bt + (size_t)(bn + r) * K + kk + q);
        }
        asm volatile("cp.async.commit_group;\n" ::);
    };

    const int NC = k_len / HBK;
    load_tiles(0, k_begin);
    load_tiles(1, k_begin + HBK);

    for (int i = 0; i < NC; ++i) {
        if (i + 1 < NC) asm volatile("cp.async.wait_group 1;\n" ::);
        else            asm volatile("cp.async.wait_group 0;\n" ::);
        __syncthreads();
        if (i + 2 < NC)
            load_tiles((i + 2) % 3, k_begin + (i + 2) * HBK);

        const uint32_t* Aw = (const uint32_t*)As + (i % 3) * (HTILE_HALVES / 2);
        const uint32_t* Bw = (const uint32_t*)Bs + (i % 3) * (HTILE_HALVES / 2);

#pragma unroll
        for (int ks = 0; ks < 2; ++ks) {
            const int kw = ks * 8;           // word offset (16 halves per ks)
            uint32_t af[4][4], bf[8][2];
#pragma unroll
            for (int mt = 0; mt < 4; ++mt) {
                const uint32_t* p = Aw + (x.rb + mt * 16 + x.g) * 20 + kw + x.c;
                af[mt][0] = p[0];
                af[mt][1] = p[8 * 20];
                af[mt][2] = p[4];
                af[mt][3] = p[8 * 20 + 4];
            }
#pragma unroll
            for (int nt = 0; nt < 8; ++nt) {
                const uint32_t* p = Bw + (x.nb + nt * 8 + x.g) * 20 + kw + x.c;
                bf[nt][0] = p[0];
                bf[nt][1] = p[4];
            }
#pragma unroll
            for (int mt = 0; mt < 4; ++mt)
#pragma unroll
                for (int nt = 0; nt < 8; ++nt)
                    mma_f16(acc[mt][nt], af[mt], bf[nt]);
        }
    }
}

// Out-projection: C[M,N] = A @ WoT^T + bias (fp32 out, no rounding)
__global__ __launch_bounds__(128, 2)
void gemm_f16(const __half* __restrict__ A, const __half* __restrict__ Bt,
              const float* __restrict__ bias, float* __restrict__ C,
              int N, int K)
{
    extern __shared__ __half smh[];
    GemmCtx x; gemm_ctx_init(x);
    const int bm = blockIdx.y * 128;
    const int bn = blockIdx.x * 128;

    float acc[4][8][4];
    gemm_zero(acc);
    gemm_core_h(A, Bt, bm, bn, K, 0, K, smh, smh + 3 * HTILE_HALVES, acc, x);

#pragma unroll
    for (int mt = 0; mt < 4; ++mt) {
        const int row0 = bm + x.rb + mt * 16 + x.g;
#pragma unroll
        for (int nt = 0; nt < 8; ++nt) {
            const int col = bn + x.nb + nt * 8 + 2 * x.c;
            const float2 bv = *(const float2*)&bias[col];
            *(float2*)&C[(size_t)row0 * N + col] =
                make_float2(acc[mt][nt][0] + bv.x, acc[mt][nt][1] + bv.y);
            *(float2*)&C[(size_t)(row0 + 8) * N + col] =
                make_float2(acc[mt][nt][2] + bv.x, acc[mt][nt][3] + bv.y);
        }
    }
}

// Fused projections, 768 CTAs:
//  cta <  384: KV split-K(x2) partial (z=cta/96: split=z>>1, V=z&1), raw fp32
//  cta >= 384: Q projection (K=768), bias + rna-tf32 epilogue -> g_Q
__global__ __launch_bounds__(128, 2)
void proj_fused(const __half* __restrict__ TgtH, const __half* __restrict__ SrcH,
                const __half* __restrict__ WqT, const float* __restrict__ bq,
                float* __restrict__ Qout,
                const __half* __restrict__ WkT, const __half* __restrict__ WvT,
                float* __restrict__ Part)
{
    extern __shared__ __half smh[];
    GemmCtx x; gemm_ctx_init(x);
    const int cta = blockIdx.x;

    float acc[4][8][4];
    gemm_zero(acc);

    if (cta < 384) {
        const int z = cta / 96;              // 0..3
        const int rem = cta % 96;
        const int bm = (rem / 6) * 128;
        const int bn = (rem % 6) * 128;
        const __half* Bt = (z & 1) ? WvT : WkT;
        float* C = Part + (size_t)z * CS * CHE;

        gemm_core_h(SrcH, Bt, bm, bn, CDL, (z >> 1) * (CDL / 2), CDL / 2,
                    smh, smh + 3 * HTILE_HALVES, acc, x);

#pragma unroll
        for (int mt = 0; mt < 4; ++mt) {
            const int row0 = bm + x.rb + mt * 16 + x.g;
#pragma unroll
            for (int nt = 0; nt < 8; ++nt) {
                const int col = bn + x.nb + nt * 8 + 2 * x.c;
                *(float2*)&C[(size_t)row0 * CHE + col] =
                    make_float2(acc[mt][nt][0], acc[mt][nt][1]);
                *(float2*)&C[(size_t)(row0 + 8) * CHE + col] =
                    make_float2(acc[mt][nt][2], acc[mt][nt][3]);
            }
        }
    } else {
        const int idx = cta - 384;
        const int bm = (idx / 6) * 128;
        const int bn = (idx % 6) * 128;

        gemm_core_h(TgtH, WqT, bm, bn, CDM, 0, CDM,
                    smh, smh + 3 * HTILE_HALVES, acc, x);

#pragma unroll
        for (int mt = 0; mt < 4; ++mt) {
            const int row0 = bm + x.rb + mt * 16 + x.g;
#pragma unroll
            for (int nt = 0; nt < 8; ++nt) {
                const int col = bn + x.nb + nt * 8 + 2 * x.c;
                const float2 bv = *(const float2*)&bq[col];
                *(float2*)&Qout[(size_t)row0 * CHE + col] =
                    make_float2(rna_tf32(acc[mt][nt][0] + bv.x),
                                rna_tf32(acc[mt][nt][1] + bv.y));
                *(float2*)&Qout[(size_t)(row0 + 8) * CHE + col] =
                    make_float2(rna_tf32(acc[mt][nt][2] + bv.x),
                                rna_tf32(acc[mt][nt][3] + bv.y));
            }
        }
    }
}

// Reduce the 2 split-K partials for K and V, add bias, rna-round (fp32 out).
__global__ void reduce_kv(const float* __restrict__ part,
                          const float* __restrict__ bk, const float* __restrict__ bv,
                          float* __restrict__ Kout, float* __restrict__ Vout)
{
    const int i4 = blockIdx.x * blockDim.x + threadIdx.x;
    const int n4 = CS * CHE / 4;
    if (i4 >= n4) return;
    const size_t MN = (size_t)CS * CHE;
    const size_t off = (size_t)i4 * 4;
    const int col = (int)(off % CHE);

    float4 sk = make_float4(0.f, 0.f, 0.f, 0.f);
    float4 sv = make_float4(0.f, 0.f, 0.f, 0.f);
#pragma unroll
    for (int s = 0; s < 2; ++s) {
        float4 pk = *(const float4*)&part[(size_t)(2 * s) * MN + off];
        float4 pv = *(const float4*)&part[(size_t)(2 * s + 1) * MN + off];
        sk.x += pk.x; sk.y += pk.y; sk.z += pk.z; sk.w += pk.w;
        sv.x += pv.x; sv.y += pv.y; sv.z += pv.z; sv.w += pv.w;
    }
    float4 bkv = *(const float4*)&bk[col];
    float4 bvv = *(const float4*)&bv[col];
    float4 ok = { rna_tf32(sk.x + bkv.x), rna_tf32(sk.y + bkv.y),
                  rna_tf32(sk.z + bkv.z), rna_tf32(sk.w + bkv.w) };
    float4 ov = { rna_tf32(sv.x + bvv.x), rna_tf32(sv.y + bvv.y),
                  rna_tf32(sv.z + bvv.z), rna_tf32(sv.w + bvv.w) };
    *(float4*)&Kout[off] = ok;
    *(float4*)&Vout[off] = ov;
}

// ============================================================================
// Tensor-core flash attention (tf32, unchanged except fp16 rep output).
// ============================================================================
#define SQ  128
#define SC  64
#define QST 100
#define KST 100
#define VST 104
#define PST 68

#define ATTN_SMEM ((SQ * QST + 2 * SC * KST + 2 * SC * VST + SQ * PST) * 4)

__global__ __launch_bounds__(256, 1)
void attn_tc()
{
    extern __shared__ float sm[];
    float* Qs = sm;
    float* Ks = Qs + SQ * QST;
    float* Vs = Ks + 2 * SC * KST;
    float* Ps = Vs + 2 * SC * VST;

    const int tid  = threadIdx.x;
    const int w    = tid >> 5;
    const int lane = tid & 31;
    const int g = lane >> 2;
    const int c = lane & 3;
    const int bh = blockIdx.y;
    const int b = bh >> 3;
    const int h = bh & 7;
    const int q0 = blockIdx.x * SQ;
    const int r0 = w * 16 + g;

    const float qs = 0.1020620726159658f * 1.4426950408889634f;

    for (int i = tid; i < SQ * (CE / 4); i += 256) {
        const int r = i / (CE / 4);
        const int c4 = (i % (CE / 4)) * 4;
        float4 v = *(const float4*)&g_Q[((size_t)(b * CL + q0 + r)) * CHE + h * CE + c4];
        Qs[r * QST + c4 + 0] = rna_tf32(v.x * qs);
        Qs[r * QST + c4 + 1] = rna_tf32(v.y * qs);
        Qs[r * QST + c4 + 2] = rna_tf32(v.z * qs);
        Qs[r * QST + c4 + 3] = rna_tf32(v.w * qs);
    }
    __syncthreads();

    uint32_t qf[12][4];
#pragma unroll
    for (int ks = 0; ks < 12; ++ks) {
        const float* p = Qs + r0 * QST + ks * 8 + c;
        qf[ks][0] = __float_as_uint(p[0]);
        qf[ks][1] = __float_as_uint(p[8 * QST]);
        qf[ks][2] = __float_as_uint(p[4]);
        qf[ks][3] = __float_as_uint(p[8 * QST + 4]);
    }

    float oacc[12][4];
#pragma unroll
    for (int nt = 0; nt < 12; ++nt)
#pragma unroll
        for (int r = 0; r < 4; ++r) oacc[nt][r] = 0.0f;
    float m0 = -1e30f, m1 = -1e30f, l0 = 0.0f, l1 = 0.0f;

    const uint32_t sKs = (uint32_t)__cvta_generic_to_shared(Ks);
    const uint32_t sVs = (uint32_t)__cvta_generic_to_shared(Vs);

    auto load_kv = [&](int bufi, int s0) {
#pragma unroll
        for (int j = 0; j < 6; ++j) {
            const int idx = tid + j * 256;
            const int r = idx / (CE / 4);
            const int c4 = (idx % (CE / 4)) * 4;
            const size_t off = ((size_t)(s0 + r)) * CHE + h * CE + c4;
            cp_async16(sKs + (bufi * SC * KST + r * KST + c4) * 4, &g_K[off]);
            cp_async16(sVs + (bufi * SC * VST + r * VST + c4) * 4, &g_V[off]);
        }
        asm volatile("cp.async.commit_group;\n" ::);
    };

    load_kv(0, 0);
    int buf = 0;

    for (int it = 0; it < CS / SC; ++it) {
        if (it + 1 < CS / SC) {
            load_kv(buf ^ 1, (it + 1) * SC);
            asm volatile("cp.async.wait_group 1;\n" ::);
        } else {
            asm volatile("cp.async.wait_group 0;\n" ::);
        }
        __syncthreads();

        const float* Kb = Ks + buf * SC * KST;
        const float* Vb = Vs + buf * SC * VST;

        float sacc[8][4];
#pragma unroll
        for (int nt = 0; nt < 8; ++nt)
#pragma unroll
            for (int r = 0; r < 4; ++r) sacc[nt][r] = 0.0f;

#pragma unroll
        for (int ks = 0; ks < 12; ++ks) {
            uint32_t kf[8][2];
#pragma unroll
            for (int nt = 0; nt < 8; ++nt) {
                const float* p = Kb + (nt * 8 + g) * KST + ks * 8 + c;
                kf[nt][0] = __float_as_uint(p[0]);
                kf[nt][1] = __float_as_uint(p[4]);
            }
#pragma unroll
            for (int nt = 0; nt < 8; ++nt)
                mma_tf32(sacc[nt], qf[ks], kf[nt]);
        }

        float cm0 = -1e30f, cm1 = -1e30f;
#pragma unroll
        for (int nt = 0; nt < 8; ++nt) {
            cm0 = fmaxf(cm0, fmaxf(sacc[nt][0], sacc[nt][1]));
            cm1 = fmaxf(cm1, fmaxf(sacc[nt][2], sacc[nt][3]));
        }
        cm0 = fmaxf(cm0, __shfl_xor_sync(0xffffffffu, cm0, 1));
        cm0 = fmaxf(cm0, __shfl_xor_sync(0xffffffffu, cm0, 2));
        cm1 = fmaxf(cm1, __shfl_xor_sync(0xffffffffu, cm1, 1));
        cm1 = fmaxf(cm1, __shfl_xor_sync(0xffffffffu, cm1, 2));

        const float nm0 = fmaxf(m0, cm0);
        const float nm1 = fmaxf(m1, cm1);
        const float sc0 = ex2(m0 - nm0);
        const float sc1 = ex2(m1 - nm1);
        m0 = nm0; m1 = nm1;

        float rs0 = 0.0f, rs1 = 0.0f;
#pragma unroll
        for (int nt = 0; nt < 8; ++nt) {
            const float p00 = ex2(sacc[nt][0] - m0);
            const float p01 = ex2(sacc[nt][1] - m0);
            const float p10 = ex2(sacc[nt][2] - m1);
            const float p11 = ex2(sacc[nt][3] - m1);
            rs0 += p00 + p01;
            rs1 += p10 + p11;
            float* pr0 = Ps + r0 * PST + nt * 8 + 2 * c;
            pr0[0] = rna_tf32(p00);
            pr0[1] = rna_tf32(p01);
            float* pr1 = Ps + (r0 + 8) * PST + nt * 8 + 2 * c;
            pr1[0] = rna_tf32(p10);
            pr1[1] = rna_tf32(p11);
        }
        rs0 += __shfl_xor_sync(0xffffffffu, rs0, 1);
        rs0 += __shfl_xor_sync(0xffffffffu, rs0, 2);
        rs1 += __shfl_xor_sync(0xffffffffu, rs1, 1);
        rs1 += __shfl_xor_sync(0xffffffffu, rs1, 2);
        l0 = l0 * sc0 + rs0;
        l1 = l1 * sc1 + rs1;

#pragma unroll
        for (int nt = 0; nt < 12; ++nt) {
            oacc[nt][0] *= sc0; oacc[nt][1] *= sc0;
            oacc[nt][2] *= sc1; oacc[nt][3] *= sc1;
        }
        __syncwarp();

#pragma unroll
        for (int ks = 0; ks < 8; ++ks) {
            uint32_t pf[4];
            const float* pp = Ps + r0 * PST + ks * 8 + c;
            pf[0] = __float_as_uint(pp[0]);
            pf[1] = __float_as_uint(pp[8 * PST]);
            pf[2] = __float_as_uint(pp[4]);
            pf[3] = __float_as_uint(pp[8 * PST + 4]);
#pragma unroll
            for (int nt = 0; nt < 12; ++nt) {
                const float* vp = Vb + (ks * 8 + c) * VST + nt * 8 + g;
                uint32_t vf[2];
                vf[0] = __float_as_uint(vp[0]);
                vf[1] = __float_as_uint(vp[4 * VST]);
                mma_tf32(oacc[nt], pf, vf);
            }
        }
        __syncthreads();
        buf ^= 1;
    }

    // Epilogue: normalize, emit fp16 rep (single rounding) for out-projection
    const float inv0 = 1.0f / l0;
    const float inv1 = 1.0f / l1;
    const size_t row0 = ((size_t)(b * CL + q0 + r0)) * CHE + h * CE;
    const size_t row1 = ((size_t)(b * CL + q0 + r0 + 8)) * CHE + h * CE;
#pragma unroll
    for (int nt = 0; nt < 12; ++nt) {
        const int col = nt * 8 + 2 * c;
        *(__half2*)&g_repH[row0 + col] =
            __floats2half2_rn(oacc[nt][0] * inv0, oacc[nt][1] * inv0);
        *(__half2*)&g_repH[row1 + col] =
            __floats2half2_rn(oacc[nt][2] * inv1, oacc[nt][3] * inv1);
    }
}

// ============================================================================
// Launch
// ============================================================================
extern "C" void kernel_launch(void* const* d_in, const int* in_sizes, int n_in,
                              void* d_out, int out_size)
{
    const float* target = (const float*)d_in[0];
    const float* source = (const float*)d_in[1];
    const float* Wq = (const float*)d_in[2];
    const float* bq = (const float*)d_in[3];
    const float* Wk = (const float*)d_in[4];
    const float* bk = (const float*)d_in[5];
    const float* Wv = (const float*)d_in[6];
    const float* bv = (const float*)d_in[7];
    const float* Wo = (const float*)d_in[8];
    const float* bo = (const float*)d_in[9];
    float* out = (float*)d_out;

    float *Qp, *Kp, *Vp, *Pp;
    __half *TgtH, *SrcH, *WqT, *WkT, *WvT, *WoT, *RepH;
    cudaGetSymbolAddress((void**)&Qp, g_Q);
    cudaGetSymbolAddress((void**)&Kp, g_K);
    cudaGetSymbolAddress((void**)&Vp, g_V);
    cudaGetSymbolAddress((void**)&Pp, g_kvpart);
    cudaGetSymbolAddress((void**)&TgtH, g_tgtH);
    cudaGetSymbolAddress((void**)&SrcH, g_srcH);
    cudaGetSymbolAddress((void**)&WqT, g_wqT);
    cudaGetSymbolAddress((void**)&WkT, g_wkT);
    cudaGetSymbolAddress((void**)&WvT, g_wvT);
    cudaGetSymbolAddress((void**)&WoT, g_woT);
    cudaGetSymbolAddress((void**)&RepH, g_repH);

    cudaFuncSetAttribute(gemm_f16, cudaFuncAttributeMaxDynamicSharedMemorySize,
                         GEMM_SMEM_H);
    cudaFuncSetAttribute(proj_fused, cudaFuncAttributeMaxDynamicSharedMemorySize,
                         GEMM_SMEM_H);
    cudaFuncSetAttribute(attn_tc, cudaFuncAttributeMaxDynamicSharedMemorySize,
                         ATTN_SMEM);

    // Stage activations to fp16
    {
        int n4 = (CB * CL * CDM) / 4;
        cvt16<<<(n4 + 255) / 256, 256>>>((const float4*)target, (__half2*)TgtH, n4);
        n4 = (CS * CDL) / 4;
        cvt16<<<(n4 + 255) / 256, 256>>>((const float4*)source, (__half2*)SrcH, n4);
    }
    // Transpose weights to [N][K] fp16
    transpose_h<<<dim3(CHE / 32, CDM / 32), dim3(32, 8)>>>(Wq, WqT, CDM, CHE);
    transpose_h<<<dim3(CHE / 32, CDL / 32), dim3(32, 8)>>>(Wk, WkT, CDL, CHE);
    transpose_h<<<dim3(CHE / 32, CDL / 32), dim3(32, 8)>>>(Wv, WvT, CDL, CHE);
    transpose_h<<<dim3(CDL / 32, CHE / 32), dim3(32, 8)>>>(Wo, WoT, CHE, CDL);

    // Fused Q projection + K/V split-K(x2) partials (768 CTAs, 128 threads)
    proj_fused<<<768, 128, GEMM_SMEM_H>>>(TgtH, SrcH, WqT, bq, Qp, WkT, WvT, Pp);

    // Reduce K/V partials (+bias, rna)
    {
        const int n4 = CS * CHE / 4;
        reduce_kv<<<(n4 + 255) / 256, 256>>>(Pp, bk, bv, Kp, Vp);
    }

    // Attention -> repH (tf32 tensor-core, fp16 epilogue)
    attn_tc<<<dim3(CL / SQ, CB * CH), dim3(256), ATTN_SMEM>>>();

    // out = rep @ Wo + bo   (8192 x 4096, K=768), fp16 mma, fp32 epilogue
    gemm_f16<<<dim3(CDL / 128, (CB * CL) / 128), 128, GEMM_SMEM_H>>>(
        RepH, WoT, bo, out, CDL, CHE);
}

// round 14
// speedup vs baseline: 1.7833x; 1.3450x over previous
#include <cuda_runtime.h>
#include <cuda_fp16.h>
#include <stdint.h>

// Problem constants
#define CB   16
#define CL   512
#define CDM  768
#define CS   2048
#define CDL  4096
#define CH   8
#define CE   96
#define CHE  768   // H*E

// Scratch (allocation-free: device globals)
__device__ __half g_QH[(size_t)CB * CL * CHE];   // Q proj, fp16, pre-scaled by 1/sqrt(E)*log2e
__device__ __half g_KH[(size_t)CS * CHE];        // K proj, fp16 [s][col]
__device__ __half g_VH[(size_t)CS * CHE];        // V proj, fp16 [s][col]
__device__ __half g_VTH[(size_t)CHE * CS];       // V transposed, fp16 [col][s]
__device__ __half g_repH[(size_t)CB * CL * CHE]; // attn output, fp16
// fp16 staged GEMM operands (A matrices [M][K], weights transposed [N][K])
__device__ __half g_tgtH[(size_t)CB * CL * CDM];
__device__ __half g_srcH[(size_t)CS * CDL];
__device__ __half g_wqT[(size_t)CHE * CDM];
__device__ __half g_wkT[(size_t)CHE * CDL];
__device__ __half g_wvT[(size_t)CHE * CDL];
__device__ __half g_woT[(size_t)CDL * CHE];
// Split-K partials for K/V projections: z in [0,4): (split = z>>1, K/V = z&1)
__device__ float g_kvpart[(size_t)4 * CS * CHE];   // 24 MB

__device__ __forceinline__ float ex2(float x) {
    float y;
    asm("ex2.approx.f32 %0, %1;" : "=f"(y) : "f"(x));
    return y;
}

__device__ __forceinline__ void mma_f16(float* d, const uint32_t* a, const uint32_t* b) {
    asm volatile(
        "mma.sync.aligned.m16n8k16.row.col.f32.f16.f16.f32 "
        "{%0,%1,%2,%3}, {%4,%5,%6,%7}, {%8,%9}, {%0,%1,%2,%3};"
        : "+f"(d[0]), "+f"(d[1]), "+f"(d[2]), "+f"(d[3])
        : "r"(a[0]), "r"(a[1]), "r"(a[2]), "r"(a[3]), "r"(b[0]), "r"(b[1]));
}

__device__ __forceinline__ void cp_async16(uint32_t dst, const void* src) {
    asm volatile("cp.async.cg.shared.global [%0], [%1], 16;\n" :: "r"(dst), "l"(src));
}

// ============================================================================
// Pre-passes
// ============================================================================
__global__ void cvt16(const float4* __restrict__ src, __half2* __restrict__ dst,
                      int n4)
{
    int i = blockIdx.x * blockDim.x + threadIdx.x;
    if (i < n4) {
        float4 v = src[i];
        dst[2 * i + 0] = __floats2half2_rn(v.x, v.y);
        dst[2 * i + 1] = __floats2half2_rn(v.z, v.w);
    }
}

__global__ void transpose_h(const float* __restrict__ in, __half* __restrict__ out,
                            int K, int N)
{
    __shared__ float t[32][33];
    const int n0 = blockIdx.x * 32;
    const int k0 = blockIdx.y * 32;
    const int xx = threadIdx.x;
    const int yy = threadIdx.y;
#pragma unroll
    for (int dy = 0; dy < 32; dy += 8)
        t[yy + dy][xx] = in[(size_t)(k0 + yy + dy) * N + n0 + xx];
    __syncthreads();
#pragma unroll
    for (int dy = 0; dy < 32; dy += 8)
        out[(size_t)(n0 + yy + dy) * K + k0 + xx] = __float2half_rn(t[xx][yy + dy]);
}

// fp16 [CS][CHE] -> fp16 [CHE][CS]
__global__ void vtrans(const __half* __restrict__ in, __half* __restrict__ out)
{
    __shared__ __half t[32][34];
    const int c0 = blockIdx.x * 32;
    const int s0 = blockIdx.y * 32;
    const int xx = threadIdx.x;
    const int yy = threadIdx.y;
#pragma unroll
    for (int dy = 0; dy < 32; dy += 8)
        t[yy + dy][xx] = in[(size_t)(s0 + yy + dy) * CHE + c0 + xx];
    __syncthreads();
#pragma unroll
    for (int dy = 0; dy < 32; dy += 8)
        out[(size_t)(c0 + yy + dy) * CS + s0 + xx] = t[xx][yy + dy];
}

// ============================================================================
// FP16 mma.sync GEMM core (m16n8k16). 128x128x32 block, 4 warps (2Mx2N),
// 64x64 warp tiles, 3-stage cp.async; tiles [128][40 halves].
// ============================================================================
#define HBK 32
#define HST 40
#define HTILE_HALVES (128 * HST)
#define HTILE_BYTES  (HTILE_HALVES * 2)
#define GEMM_SMEM_H  (3 * 2 * HTILE_BYTES)

struct GemmCtx { int tid, rb, nb, g, c; };

__device__ __forceinline__ void gemm_ctx_init(GemmCtx& x) {
    const int tid = threadIdx.x;
    const int wid = tid >> 5;
    const int lane = tid & 31;
    x.tid = tid;
    x.rb = (wid & 1) * 64;
    x.nb = (wid >> 1) * 64;
    x.g = lane >> 2;
    x.c = lane & 3;
}

__device__ __forceinline__ void gemm_zero(float acc[4][8][4]) {
#pragma unroll
    for (int mt = 0; mt < 4; ++mt)
#pragma unroll
        for (int nt = 0; nt < 8; ++nt)
#pragma unroll
            for (int r = 0; r < 4; ++r) acc[mt][nt][r] = 0.0f;
}

__device__ __forceinline__ void gemm_core_h(
    const __half* __restrict__ A, const __half* __restrict__ Bt,
    int bm, int bn, int K, int k_begin, int k_len,
    __half* As, __half* Bs, float acc[4][8][4], const GemmCtx& x)
{
    const uint32_t sA = (uint32_t)__cvta_generic_to_shared(As);
    const uint32_t sB = (uint32_t)__cvta_generic_to_shared(Bs);
    const int tid = x.tid;

    auto load_tiles = [&](int stg, int kk) {
        const uint32_t ab = sA + stg * HTILE_BYTES;
        const uint32_t bb = sB + stg * HTILE_BYTES;
#pragma unroll
        for (int j = 0; j < 4; ++j) {
            const int idx = tid + j * 128;
            const int r = idx >> 2;
            const int q = (idx & 3) << 3;
            cp_async16(ab + (r * HST + q) * 2, A + (size_t)(bm + r) * K + kk + q);
            cp_async16(bb + (r * HST + q) * 2, Bt + (size_t)(bn + r) * K + kk + q);
        }
        asm volatile("cp.async.commit_group;\n" ::);
    };

    const int NC = k_len / HBK;
    load_tiles(0, k_begin);
    load_tiles(1, k_begin + HBK);

    for (int i = 0; i < NC; ++i) {
        if (i + 1 < NC) asm volatile("cp.async.wait_group 1;\n" ::);
        else            asm volatile("cp.async.wait_group 0;\n" ::);
        __syncthreads();
        if (i + 2 < NC)
            load_tiles((i + 2) % 3, k_begin + (i + 2) * HBK);

        const uint32_t* Aw = (const uint32_t*)As + (i % 3) * (HTILE_HALVES / 2);
        const uint32_t* Bw = (const uint32_t*)Bs + (i % 3) * (HTILE_HALVES / 2);

#pragma unroll
        for (int ks = 0; ks < 2; ++ks) {
            const int kw = ks * 8;
            uint32_t af[4][4], bf[8][2];
#pragma unroll
            for (int mt = 0; mt < 4; ++mt) {
                const uint32_t* p = Aw + (x.rb + mt * 16 + x.g) * 20 + kw + x.c;
                af[mt][0] = p[0];
                af[mt][1] = p[8 * 20];
                af[mt][2] = p[4];
                af[mt][3] = p[8 * 20 + 4];
            }
#pragma unroll
            for (int nt = 0; nt < 8; ++nt) {
                const uint32_t* p = Bw + (x.nb + nt * 8 + x.g) * 20 + kw + x.c;
                bf[nt][0] = p[0];
                bf[nt][1] = p[4];
            }
#pragma unroll
            for (int mt = 0; mt < 4; ++mt)
#pragma unroll
                for (int nt = 0; nt < 8; ++nt)
                    mma_f16(acc[mt][nt], af[mt], bf[nt]);
        }
    }
}

// Out-projection: C[M,N] = A @ WoT^T + bias (fp32 out)
__global__ __launch_bounds__(128, 2)
void gemm_f16(const __half* __restrict__ A, const __half* __restrict__ Bt,
              const float* __restrict__ bias, float* __restrict__ C,
              int N, int K)
{
    extern __shared__ __half smh[];
    GemmCtx x; gemm_ctx_init(x);
    const int bm = blockIdx.y * 128;
    const int bn = blockIdx.x * 128;

    float acc[4][8][4];
    gemm_zero(acc);
    gemm_core_h(A, Bt, bm, bn, K, 0, K, smh, smh + 3 * HTILE_HALVES, acc, x);

#pragma unroll
    for (int mt = 0; mt < 4; ++mt) {
        const int row0 = bm + x.rb + mt * 16 + x.g;
#pragma unroll
        for (int nt = 0; nt < 8; ++nt) {
            const int col = bn + x.nb + nt * 8 + 2 * x.c;
            const float2 bv = *(const float2*)&bias[col];
            *(float2*)&C[(size_t)row0 * N + col] =
                make_float2(acc[mt][nt][0] + bv.x, acc[mt][nt][1] + bv.y);
            *(float2*)&C[(size_t)(row0 + 8) * N + col] =
                make_float2(acc[mt][nt][2] + bv.x, acc[mt][nt][3] + bv.y);
        }
    }
}

// Fused projections, 768 CTAs:
//  cta <  384: KV split-K(x2) partial (z=cta/96: split=z>>1, V=z&1), raw fp32
//  cta >= 384: Q projection (K=768), bias + softmax-scale + fp16 epilogue
__global__ __launch_bounds__(128, 2)
void proj_fused(const __half* __restrict__ TgtH, const __half* __restrict__ SrcH,
                const __half* __restrict__ WqT, const float* __restrict__ bq,
                __half* __restrict__ QoutH,
                const __half* __restrict__ WkT, const __half* __restrict__ WvT,
                float* __restrict__ Part)
{
    extern __shared__ __half smh[];
    GemmCtx x; gemm_ctx_init(x);
    const int cta = blockIdx.x;

    float acc[4][8][4];
    gemm_zero(acc);

    if (cta < 384) {
        const int z = cta / 96;
        const int rem = cta % 96;
        const int bm = (rem / 6) * 128;
        const int bn = (rem % 6) * 128;
        const __half* Bt = (z & 1) ? WvT : WkT;
        float* C = Part + (size_t)z * CS * CHE;

        gemm_core_h(SrcH, Bt, bm, bn, CDL, (z >> 1) * (CDL / 2), CDL / 2,
                    smh, smh + 3 * HTILE_HALVES, acc, x);

#pragma unroll
        for (int mt = 0; mt < 4; ++mt) {
            const int row0 = bm + x.rb + mt * 16 + x.g;
#pragma unroll
            for (int nt = 0; nt < 8; ++nt) {
                const int col = bn + x.nb + nt * 8 + 2 * x.c;
                *(float2*)&C[(size_t)row0 * CHE + col] =
                    make_float2(acc[mt][nt][0], acc[mt][nt][1]);
                *(float2*)&C[(size_t)(row0 + 8) * CHE + col] =
                    make_float2(acc[mt][nt][2], acc[mt][nt][3]);
            }
        }
    } else {
        const int idx = cta - 384;
        const int bm = (idx / 6) * 128;
        const int bn = (idx % 6) * 128;
        const float QS = 0.1020620726159658f * 1.4426950408889634f;

        gemm_core_h(TgtH, WqT, bm, bn, CDM, 0, CDM,
                    smh, smh + 3 * HTILE_HALVES, acc, x);

#pragma unroll
        for (int mt = 0; mt < 4; ++mt) {
            const int row0 = bm + x.rb + mt * 16 + x.g;
#pragma unroll
            for (int nt = 0; nt < 8; ++nt) {
                const int col = bn + x.nb + nt * 8 + 2 * x.c;
                const float2 bv = *(const float2*)&bq[col];
                *(__half2*)&QoutH[(size_t)row0 * CHE + col] =
                    __floats2half2_rn((acc[mt][nt][0] + bv.x) * QS,
                                      (acc[mt][nt][1] + bv.y) * QS);
                *(__half2*)&QoutH[(size_t)(row0 + 8) * CHE + col] =
                    __floats2half2_rn((acc[mt][nt][2] + bv.x) * QS,
                                      (acc[mt][nt][3] + bv.y) * QS);
            }
        }
    }
}

// Reduce the 2 split-K partials for K and V, add bias, emit fp16.
__global__ void reduce_kv(const float* __restrict__ part,
                          const float* __restrict__ bk, const float* __restrict__ bv,
                          __half* __restrict__ KoutH, __half* __restrict__ VoutH)
{
    const int i4 = blockIdx.x * blockDim.x + threadIdx.x;
    const int n4 = CS * CHE / 4;
    if (i4 >= n4) return;
    const size_t MN = (size_t)CS * CHE;
    const size_t off = (size_t)i4 * 4;
    const int col = (int)(off % CHE);

    float4 sk = make_float4(0.f, 0.f, 0.f, 0.f);
    float4 sv = make_float4(0.f, 0.f, 0.f, 0.f);
#pragma unroll
    for (int s = 0; s < 2; ++s) {
        float4 pk = *(const float4*)&part[(size_t)(2 * s) * MN + off];
        float4 pv = *(const float4*)&part[(size_t)(2 * s + 1) * MN + off];
        sk.x += pk.x; sk.y += pk.y; sk.z += pk.z; sk.w += pk.w;
        sv.x += pv.x; sv.y += pv.y; sv.z += pv.z; sv.w += pv.w;
    }
    float4 bkv = *(const float4*)&bk[col];
    float4 bvv = *(const float4*)&bv[col];
    *(__half2*)&KoutH[off + 0] = __floats2half2_rn(sk.x + bkv.x, sk.y + bkv.y);
    *(__half2*)&KoutH[off + 2] = __floats2half2_rn(sk.z + bkv.z, sk.w + bkv.w);
    *(__half2*)&VoutH[off + 0] = __floats2half2_rn(sv.x + bvv.x, sv.y + bvv.y);
    *(__half2*)&VoutH[off + 2] = __floats2half2_rn(sv.z + bvv.z, sv.w + bvv.w);
}

// ============================================================================
// FP16 tensor-core flash attention.
// CTA = one (b,h) x 128-query tile; 8 warps x 16 query rows each.
// QK^T and PV via mma.sync m16n8k16; V pre-transposed in gmem.
// Strides: Q/K 104 halves (52w: banks 20g+c), VT/P 72 halves (36w: banks 4g+c).
// ============================================================================
#define SQ  128
#define SC  64
#define QSH 104
#define KSH 104
#define VSH 72
#define PSH 72

#define ATTN_SMEM_H ((SQ * QSH + 2 * SC * KSH + 2 * CE * VSH + SQ * PSH) * 2)

__global__ __launch_bounds__(256, 1)
void attn_h()
{
    extern __shared__ __half smh[];
    __half* Qs = smh;                        // 128 x 104
    __half* Ks = Qs + SQ * QSH;              // 2 x 64 x 104
    __half* Vs = Ks + 2 * SC * KSH;          // 2 x 96 x 72 (transposed: [e][s])
    __half* Ps = Vs + 2 * CE * VSH;          // 128 x 72

    const int tid  = threadIdx.x;
    const int w    = tid >> 5;
    const int lane = tid & 31;
    const int g = lane >> 2;
    const int c = lane & 3;
    const int bh = blockIdx.y;
    const int b = bh >> 3;
    const int h = bh & 7;
    const int q0 = blockIdx.x * SQ;
    const int r0 = w * 16 + g;

    const uint32_t sQ = (uint32_t)__cvta_generic_to_shared(Qs);
    const uint32_t sK = (uint32_t)__cvta_generic_to_shared(Ks);
    const uint32_t sV = (uint32_t)__cvta_generic_to_shared(Vs);

    // Load Q tile (pre-scaled fp16): 128 rows x 96 halves
#pragma unroll
    for (int j = 0; j < 6; ++j) {
        const int idx = tid + j * 256;           // 0..1535
        const int r = idx / 12;
        const int q8 = (idx % 12) * 8;
        cp_async16(sQ + (r * QSH + q8) * 2,
                   &g_QH[((size_t)(b * CL + q0 + r)) * CHE + h * CE + q8]);
    }
    asm volatile("cp.async.commit_group;\n" ::);

    auto load_kv = [&](int bufi, int s0) {
#pragma unroll
        for (int j = 0; j < 3; ++j) {
            const int idx = tid + j * 256;       // 0..767
            const int rk = idx / 12;             // 0..63
            const int qk = (idx % 12) * 8;
            cp_async16(sK + (bufi * SC * KSH + rk * KSH + qk) * 2,
                       &g_KH[((size_t)(s0 + rk)) * CHE + h * CE + qk]);
            const int rv = idx / 8;              // 0..95
            const int qv = (idx % 8) * 8;
            cp_async16(sV + (bufi * CE * VSH + rv * VSH + qv) * 2,
                       &g_VTH[((size_t)(h * CE + rv)) * CS + s0 + qv]);
        }
        asm volatile("cp.async.commit_group;\n" ::);
    };

    load_kv(0, 0);
    // Wait for Q (and chunk0), hoist Q fragments for the whole S loop
    asm volatile("cp.async.wait_group 0;\n" ::);
    __syncthreads();

    uint32_t qf[6][4];
    {
        const uint32_t* Qw = (const uint32_t*)Qs;
#pragma unroll
        for (int ks = 0; ks < 6; ++ks) {
            const uint32_t* p = Qw + r0 * (QSH / 2) + ks * 8 + c;
            qf[ks][0] = p[0];
            qf[ks][1] = p[8 * (QSH / 2)];
            qf[ks][2] = p[4];
            qf[ks][3] = p[8 * (QSH / 2) + 4];
        }
    }

    float oacc[12][4];
#pragma unroll
    for (int nt = 0; nt < 12; ++nt)
#pragma unroll
        for (int r = 0; r < 4; ++r) oacc[nt][r] = 0.0f;
    float m0 = -1e30f, m1 = -1e30f, l0 = 0.0f, l1 = 0.0f;

    int buf = 0;
    for (int it = 0; it < CS / SC; ++it) {
        if (it + 1 < CS / SC) {
            load_kv(buf ^ 1, (it + 1) * SC);
            asm volatile("cp.async.wait_group 1;\n" ::);
        } else {
            asm volatile("cp.async.wait_group 0;\n" ::);
        }
        __syncthreads();

        const uint32_t* Kw = (const uint32_t*)Ks + buf * SC * (KSH / 2);
        const uint32_t* Vw = (const uint32_t*)Vs + buf * CE * (VSH / 2);

        // ---- QK^T (fp16): 16x64 scores per warp ----
        float sacc[8][4];
#pragma unroll
        for (int nt = 0; nt < 8; ++nt)
#pragma unroll
            for (int r = 0; r < 4; ++r) sacc[nt][r] = 0.0f;

#pragma unroll
        for (int ks = 0; ks < 6; ++ks) {
            uint32_t kf[8][2];
#pragma unroll
            for (int nt = 0; nt < 8; ++nt) {
                const uint32_t* p = Kw + (nt * 8 + g) * (KSH / 2) + ks * 8 + c;
                kf[nt][0] = p[0];
                kf[nt][1] = p[4];
            }
#pragma unroll
            for (int nt = 0; nt < 8; ++nt)
                mma_f16(sacc[nt], qf[ks], kf[nt]);
        }

        // ---- online softmax (rows r0, r0+8; quad-local reductions) ----
        float cm0 = -1e30f, cm1 = -1e30f;
#pragma unroll
        for (int nt = 0; nt < 8; ++nt) {
            cm0 = fmaxf(cm0, fmaxf(sacc[nt][0], sacc[nt][1]));
            cm1 = fmaxf(cm1, fmaxf(sacc[nt][2], sacc[nt][3]));
        }
        cm0 = fmaxf(cm0, __shfl_xor_sync(0xffffffffu, cm0, 1));
        cm0 = fmaxf(cm0, __shfl_xor_sync(0xffffffffu, cm0, 2));
        cm1 = fmaxf(cm1, __shfl_xor_sync(0xffffffffu, cm1, 1));
        cm1 = fmaxf(cm1, __shfl_xor_sync(0xffffffffu, cm1, 2));

        const float nm0 = fmaxf(m0, cm0);
        const float nm1 = fmaxf(m1, cm1);
        const float sc0 = ex2(m0 - nm0);
        const float sc1 = ex2(m1 - nm1);
        m0 = nm0; m1 = nm1;

        float rs0 = 0.0f, rs1 = 0.0f;
#pragma unroll
        for (int nt = 0; nt < 8; ++nt) {
            const float p00 = ex2(sacc[nt][0] - m0);
            const float p01 = ex2(sacc[nt][1] - m0);
            const float p10 = ex2(sacc[nt][2] - m1);
            const float p11 = ex2(sacc[nt][3] - m1);
            rs0 += p00 + p01;
            rs1 += p10 + p11;
            *(__half2*)&Ps[r0 * PSH + nt * 8 + 2 * c] = __floats2half2_rn(p00, p01);
            *(__half2*)&Ps[(r0 + 8) * PSH + nt * 8 + 2 * c] = __floats2half2_rn(p10, p11);
        }
        rs0 += __shfl_xor_sync(0xffffffffu, rs0, 1);
        rs0 += __shfl_xor_sync(0xffffffffu, rs0, 2);
        rs1 += __shfl_xor_sync(0xffffffffu, rs1, 1);
        rs1 += __shfl_xor_sync(0xffffffffu, rs1, 2);
        l0 = l0 * sc0 + rs0;
        l1 = l1 * sc1 + rs1;

#pragma unroll
        for (int nt = 0; nt < 12; ++nt) {
            oacc[nt][0] *= sc0; oacc[nt][1] *= sc0;
            oacc[nt][2] *= sc1; oacc[nt][3] *= sc1;
        }
        __syncwarp();

        // ---- PV (fp16): O[16x96] += P[16x64] @ V[64x96] (V transposed) ----
        const uint32_t* Pw = (const uint32_t*)Ps;
#pragma unroll
        for (int ks = 0; ks < 4; ++ks) {
            uint32_t af[4];
            const uint32_t* pp = Pw + r0 * (PSH / 2) + ks * 8 + c;
            af[0] = pp[0];
            af[1] = pp[8 * (PSH / 2)];
            af[2] = pp[4];
            af[3] = pp[8 * (PSH / 2) + 4];
#pragma unroll
            for (int nt = 0; nt < 12; ++nt) {
                const uint32_t* vp = Vw + (nt * 8 + g) * (VSH / 2) + ks * 8 + c;
                uint32_t bf[2] = { vp[0], vp[4] };
                mma_f16(oacc[nt], af, bf);
            }
        }
        __syncthreads();
        buf ^= 1;
    }

    // ---- epilogue: normalize, emit fp16 rep for out-projection ----
    const float inv0 = 1.0f / l0;
    const float inv1 = 1.0f / l1;
    const size_t row0 = ((size_t)(b * CL + q0 + r0)) * CHE + h * CE;
    const size_t row1 = ((size_t)(b * CL + q0 + r0 + 8)) * CHE + h * CE;
#pragma unroll
    for (int nt = 0; nt < 12; ++nt) {
        const int col = nt * 8 + 2 * c;
        *(__half2*)&g_repH[row0 + col] =
            __floats2half2_rn(oacc[nt][0] * inv0, oacc[nt][1] * inv0);
        *(__half2*)&g_repH[row1 + col] =
            __floats2half2_rn(oacc[nt][2] * inv1, oacc[nt][3] * inv1);
    }
}

// ============================================================================
// Launch
// ============================================================================
extern "C" void kernel_launch(void* const* d_in, const int* in_sizes, int n_in,
                              void* d_out, int out_size)
{
    const float* target = (const float*)d_in[0];
    const float* source = (const float*)d_in[1];
    const float* Wq = (const float*)d_in[2];
    const float* bq = (const float*)d_in[3];
    const float* Wk = (const float*)d_in[4];
    const float* bk = (const float*)d_in[5];
    const float* Wv = (const float*)d_in[6];
    const float* bv = (const float*)d_in[7];
    const float* Wo = (const float*)d_in[8];
    const float* bo = (const float*)d_in[9];
    float* out = (float*)d_out;

    float* Pp;
    __half *TgtH, *SrcH, *WqT, *WkT, *WvT, *WoT, *RepH, *QH, *KH, *VH, *VTH;
    cudaGetSymbolAddress((void**)&Pp, g_kvpart);
    cudaGetSymbolAddress((void**)&TgtH, g_tgtH);
    cudaGetSymbolAddress((void**)&SrcH, g_srcH);
    cudaGetSymbolAddress((void**)&WqT, g_wqT);
    cudaGetSymbolAddress((void**)&WkT, g_wkT);
    cudaGetSymbolAddress((void**)&WvT, g_wvT);
    cudaGetSymbolAddress((void**)&WoT, g_woT);
    cudaGetSymbolAddress((void**)&RepH, g_repH);
    cudaGetSymbolAddress((void**)&QH, g_QH);
    cudaGetSymbolAddress((void**)&KH, g_KH);
    cudaGetSymbolAddress((void**)&VH, g_VH);
    cudaGetSymbolAddress((void**)&VTH, g_VTH);

    cudaFuncSetAttribute(gemm_f16, cudaFuncAttributeMaxDynamicSharedMemorySize,
                         GEMM_SMEM_H);
    cudaFuncSetAttribute(proj_fused, cudaFuncAttributeMaxDynamicSharedMemorySize,
                         GEMM_SMEM_H);
    cudaFuncSetAttribute(attn_h, cudaFuncAttributeMaxDynamicSharedMemorySize,
                         ATTN_SMEM_H);

    // Stage activations to fp16
    {
        int n4 = (CB * CL * CDM) / 4;
        cvt16<<<(n4 + 255) / 256, 256>>>((const float4*)target, (__half2*)TgtH, n4);
        n4 = (CS * CDL) / 4;
        cvt16<<<(n4 + 255) / 256, 256>>>((const float4*)source, (__half2*)SrcH, n4);
    }
    // Transpose weights to [N][K] fp16
    transpose_h<<<dim3(CHE / 32, CDM / 32), dim3(32, 8)>>>(Wq, WqT, CDM, CHE);
    transpose_h<<<dim3(CHE / 32, CDL / 32), dim3(32, 8)>>>(Wk, WkT, CDL, CHE);
    transpose_h<<<dim3(CHE / 32, CDL / 32), dim3(32, 8)>>>(Wv, WvT, CDL, CHE);
    transpose_h<<<dim3(CDL / 32, CHE / 32), dim3(32, 8)>>>(Wo, WoT, CHE, CDL);

    // Fused Q projection (fp16, pre-scaled) + K/V split-K(x2) partials
    proj_fused<<<768, 128, GEMM_SMEM_H>>>(TgtH, SrcH, WqT, bq, QH, WkT, WvT, Pp);

    // Reduce K/V partials (+bias) -> fp16
    {
        const int n4 = CS * CHE / 4;
        reduce_kv<<<(n4 + 255) / 256, 256>>>(Pp, bk, bv, KH, VH);
    }
    // Transpose V for PV mma B-operand
    vtrans<<<dim3(CHE / 32, CS / 32), dim3(32, 8)>>>(VH, VTH);

    // Attention -> repH (fp16 tensor-core)
    attn_h<<<dim3(CL / SQ, CB * CH), dim3(256), ATTN_SMEM_H>>>();

    // out = rep @ Wo + bo   (8192 x 4096, K=768), fp16 mma, fp32 epilogue
    gemm_f16<<<dim3(CDL / 128, (CB * CL) / 128), 128, GEMM_SMEM_H>>>(
        RepH, WoT, bo, out, CDL, CHE);
}